// round 11
// baseline (speedup 1.0000x reference)
#include <cuda_runtime.h>
#include <cuda_fp16.h>
#include <cstdint>

// NAryTreeLSTMCell — round 11: chain-free f16-accumulate probe.
// r8/r10 sit at an elapsed floor of ~16 cyc/HMMA/SMSP while the pipe-busy rate
// is ~8 — hypothesis: f32-acc D/C operand width halves sustainable issue; r9's
// f16-acc test failed only because of 4-spaced serial D chains. This kernel:
// f16 chunk partials with 10-wide D independence (ks-outer/np-inner), fp32
// masters promoted per 128-K chunk, BM=64 tile so everything fits in 128 regs.
// ARITY=2, LABEL_DIM=128, H_DIM=512, B=16384, ARG_DIM=1152.

namespace {
constexpr int Bsz = 16384;
constexpr int H   = 512;
constexpr int L   = 128;
constexpr int K   = 1152;
constexpr int NG  = 5;
constexpr int BM  = 64;            // batch rows / CTA
constexpr int BNR = 320;           // B rows: 5 gates x 64 h
constexpr int BHh = 64;            // h per gate per CTA
constexpr int BK  = 128;           // K per chunk
constexpr int NCHUNK = K / BK;     // 9
constexpr int THREADS = 512;       // 16 warps: 4(m) x 4(n), warp tile 16x80

constexpr uint32_t AG = BM * 16;    // 1024
constexpr uint32_t BG = BNR * 16;   // 5120
constexpr uint32_t A_TILE = 16 * AG;               // 16384 B
constexpr uint32_t B_TILE = 16 * BG;               // 81920 B
constexpr uint32_t OFF_A = 0;
constexpr uint32_t OFF_B = A_TILE;
constexpr uint32_t STAGE_BYTES = A_TILE + B_TILE;  // 98304
constexpr uint32_t SMEM_TOTAL  = 2 * STAGE_BYTES + 64;   // 196672

constexpr int NX = Bsz * (K / 4);
constexpr int NW = NG * H * (K / 4);
} // namespace

// ---- scratch: chunk-tiled, granule-blocked images (exact SMEM layout) ----
__device__ __half g_Xt[(size_t)NCHUNK * (Bsz / BM) * (A_TILE / 2)];
__device__ __half g_Wt[(size_t)NCHUNK * (H / BHh) * (B_TILE / 2)];

// ---- PTX helpers ----
__device__ __forceinline__ uint32_t smem_u32(const void* p) {
    return (uint32_t)__cvta_generic_to_shared(p);
}
__device__ __forceinline__ void bulk_cp(uint32_t dst, const void* src,
                                        uint32_t bytes, uint32_t mbar) {
    asm volatile("cp.async.bulk.shared::cta.global.mbarrier::complete_tx::bytes "
                 "[%0], [%1], %2, [%3];"
                 :: "r"(dst), "l"(src), "r"(bytes), "r"(mbar) : "memory");
}
__device__ __forceinline__ void mbar_init(uint32_t a, uint32_t cnt) {
    asm volatile("mbarrier.init.shared.b64 [%0], %1;" :: "r"(a), "r"(cnt) : "memory");
}
__device__ __forceinline__ void mbar_expect(uint32_t a, uint32_t bytes) {
    asm volatile("mbarrier.arrive.expect_tx.shared::cta.b64 _, [%0], %1;"
                 :: "r"(a), "r"(bytes) : "memory");
}
__device__ __forceinline__ void mbar_wait(uint32_t a, uint32_t ph) {
    asm volatile("{\n.reg .pred P;\nLW%=:\n"
                 "mbarrier.try_wait.parity.shared::cta.b64 P, [%0], %1;\n"
                 "@!P bra LW%=;\n}" :: "r"(a), "r"(ph) : "memory");
}
__device__ __forceinline__ void ldsm4(uint32_t* r, uint32_t a) {
    asm volatile("ldmatrix.sync.aligned.m8n8.x4.shared.b16 {%0,%1,%2,%3}, [%4];"
                 : "=r"(r[0]), "=r"(r[1]), "=r"(r[2]), "=r"(r[3]) : "r"(a));
}
// f16-accumulate mma: D,C are 2x f16x2 regs
__device__ __forceinline__ void mma_f16acc(uint32_t* d, const uint32_t* a,
                                           const uint32_t* b) {
    asm volatile("mma.sync.aligned.m16n8k16.row.col.f16.f16.f16.f16 "
                 "{%0,%1}, {%2,%3,%4,%5}, {%6,%7}, {%0,%1};"
                 : "+r"(d[0]), "+r"(d[1])
                 : "r"(a[0]), "r"(a[1]), "r"(a[2]), "r"(a[3]), "r"(b[0]), "r"(b[1]));
}
__device__ __forceinline__ float sigmf(float x) { return 1.0f / (1.0f + __expf(-x)); }

// ---- merged pack kernel: fp32 -> fp16 tile images for X and W ----
__global__ void pack_all(const float* __restrict__ label, const float* __restrict__ ch_h,
                         const float* __restrict__ Wi, const float* __restrict__ Wo,
                         const float* __restrict__ Wu, const float* __restrict__ Wfl,
                         const float* __restrict__ Wfs) {
    int i = blockIdx.x * blockDim.x + threadIdx.x;
    if (i < NX) {
        int b = i / (K / 4);
        int d = (i % (K / 4)) * 4;
        const float* src;
        if (d < L) src = label + (size_t)b * L + d;
        else {
            int dd = d - L; int j = dd >> 9; int hh = dd & 511;
            src = ch_h + (((size_t)(j * Bsz + b)) << 9) + hh;
        }
        float4 v = *reinterpret_cast<const float4*>(src);
        __half h4[4] = {__float2half_rn(v.x), __float2half_rn(v.y),
                        __float2half_rn(v.z), __float2half_rn(v.w)};
        int c  = d >> 7, kk = d & 127, g = kk >> 3;
        int mt = b >> 6, r = b & 63;          // 64-row m-tiles
        size_t o = ((size_t)(c * 256 + mt)) * (A_TILE / 2) + (size_t)g * 512 + r * 8 + (kk & 7);
        *reinterpret_cast<uint2*>(&g_Xt[o]) = *reinterpret_cast<uint2*>(h4);
    } else if (i < NX + NW) {
        int u  = i - NX;
        int rw = u / (K / 4);
        int d  = (u % (K / 4)) * 4;
        int gate = rw >> 9, h = rw & 511;
        const float* src;
        if (gate == 0)      src = Wi + (size_t)h * K + d;
        else if (gate == 1) src = Wo + (size_t)h * K + d;
        else if (gate == 2) src = Wu + (size_t)h * K + d;
        else if (d < L)     src = Wfl + (size_t)h * L + d;
        else {
            int dd = d - L; int j = dd >> 9; int hh = dd & 511;
            src = Wfs + (((size_t)(((gate - 3) * 2 + j) * H + h)) << 9) + hh;
        }
        float4 v = *reinterpret_cast<const float4*>(src);
        __half h4[4] = {__float2half_rn(v.x), __float2half_rn(v.y),
                        __float2half_rn(v.z), __float2half_rn(v.w)};
        int c   = d >> 7, kk = d & 127, g = kk >> 3;
        int bht = h >> 6;
        int rr  = gate * 64 + (h & 63);
        size_t o = ((size_t)(c * 8 + bht)) * (B_TILE / 2) + (size_t)g * 2560 + rr * 8 + (kk & 7);
        *reinterpret_cast<uint2*>(&g_Wt[o]) = *reinterpret_cast<uint2*>(h4);
    }
}

// ---- main kernel ----
__global__ __launch_bounds__(THREADS, 1)
void treelstm_mma(const float* __restrict__ ch_c,
                  const float* __restrict__ b_i, const float* __restrict__ b_o,
                  const float* __restrict__ b_u, const float* __restrict__ fbias,
                  float* __restrict__ out) {
    extern __shared__ char smem[];
    const uint32_t sbase = smem_u32(smem);
    const int tid  = threadIdx.x;
    const int wid  = tid >> 5, lane = tid & 31;
    const int wm   = wid & 3;          // 4 m-warps (16 rows each)
    const int wn   = wid >> 2;         // 4 n-warps (80 cols each)
    const int bht  = blockIdx.x;
    const int mt   = blockIdx.y;
    const int bh0  = bht * BHh;
    const int bm0  = mt * BM;

    const uint32_t STG0 = sbase;
    const uint32_t STG1 = sbase + STAGE_BYTES;
    const uint32_t mb0  = sbase + 2 * STAGE_BYTES;
    const uint32_t mb1  = mb0 + 16;

    const char* Abase = reinterpret_cast<const char*>(g_Xt);
    const char* Bbase = reinterpret_cast<const char*>(g_Wt);
    auto Asrc = [&](int c) { return Abase + ((size_t)(c * 256 + mt)) * A_TILE; };
    auto Bsrc = [&](int c) { return Bbase + ((size_t)(c * 8 + bht)) * B_TILE; };

    if (tid == 0) { mbar_init(mb0, 1); mbar_init(mb1, 1); }
    __syncthreads();
    if (tid == 0) {
        mbar_expect(mb0, STAGE_BYTES);
        bulk_cp(STG0 + OFF_A, Asrc(0), A_TILE, mb0);
        bulk_cp(STG0 + OFF_B, Bsrc(0), B_TILE, mb0);
        mbar_expect(mb1, STAGE_BYTES);
        bulk_cp(STG1 + OFF_A, Asrc(1), A_TILE, mb1);
        bulk_cp(STG1 + OFF_B, Bsrc(1), B_TILE, mb1);
    }

    // ldmatrix lane addressing (granule-blocked, no swizzle)
    const int ar  = ((lane >> 3) & 1) * 8 + (lane & 7);
    const uint32_t aBase = (uint32_t)((wm * 16 + ar) * 16) + (uint32_t)(lane >> 4) * AG;
    const int br  = ((lane >> 4) & 1) * 8 + (lane & 7);
    const uint32_t bBase = (uint32_t)((wn * 80 + br) * 16) + (uint32_t)((lane >> 3) & 1) * BG;

    float acc[10][4];                  // fp32 masters (warp tile 16x80)
    #pragma unroll
    for (int ni = 0; ni < 10; ni++)
        #pragma unroll
        for (int q = 0; q < 4; q++) acc[ni][q] = 0.0f;

    uint32_t ph0 = 0, ph1 = 0;
    for (int k = 0; k < NCHUNK; k++) {
        const int s = k & 1;
        const uint32_t stg = s ? STG1 : STG0;
        if (s) { mbar_wait(mb1, ph1); ph1 ^= 1; }
        else   { mbar_wait(mb0, ph0); ph0 ^= 1; }

        uint32_t d[20];                // f16x2 chunk partials, 10 independent tiles
        #pragma unroll
        for (int q = 0; q < 20; q++) d[q] = 0u;

        uint32_t a[2][4], b[2][4];
        ldsm4(a[0], stg + OFF_A + aBase);
        ldsm4(b[0], stg + OFF_B + bBase);
        #pragma unroll
        for (int it = 0; it < 40; it++) {
            const int ks = it / 5, np = it % 5;
            const int ca = ks & 1, cb = it & 1;
            if (it + 1 < 40) {
                const int ks2 = (it + 1) / 5, np2 = (it + 1) % 5;
                ldsm4(b[1 - cb], stg + OFF_B + bBase
                                 + (uint32_t)(2 * ks2) * BG + (uint32_t)np2 * 256);
                if (np2 == 0)
                    ldsm4(a[ks2 & 1], stg + OFF_A + aBase + (uint32_t)(2 * ks2) * AG);
            }
            // two mma per it; same-d reuse spacing = 10 mma (chain-free)
            mma_f16acc(d + 4 * np + 0, a[ca], b[cb] + 0);
            mma_f16acc(d + 4 * np + 2, a[ca], b[cb] + 2);
        }
        // promote f16 partials -> fp32 masters (once per 128-K chunk)
        #pragma unroll
        for (int ni = 0; ni < 10; ni++) {
            float2 lo = __half22float2(*reinterpret_cast<const __half2*>(&d[2 * ni + 0]));
            float2 hi = __half22float2(*reinterpret_cast<const __half2*>(&d[2 * ni + 1]));
            acc[ni][0] += lo.x;
            acc[ni][1] += lo.y;
            acc[ni][2] += hi.x;
            acc[ni][3] += hi.y;
        }
        __syncthreads();                            // stage s fully consumed
        if (k + 2 < NCHUNK && tid == 0) {
            const uint32_t mb = s ? mb1 : mb0;
            mbar_expect(mb, STAGE_BYTES);
            bulk_cp(stg + OFF_A, Asrc(k + 2), A_TILE, mb);
            bulk_cp(stg + OFF_B, Bsrc(k + 2), B_TILE, mb);
        }
    }

    // ---- epilogue: recombine gates through SMEM ----
    __syncthreads();
    float* gbuf = reinterpret_cast<float*>(smem);   // [320][65]
    #pragma unroll
    for (int ni = 0; ni < 10; ni++) {
        const int m = wm * 16 + (lane >> 2);
        const int n = wn * 80 + ni * 8 + 2 * (lane & 3);
        gbuf[(size_t)n * 65 + m]           = acc[ni][0];
        gbuf[(size_t)(n + 1) * 65 + m]     = acc[ni][1];
        gbuf[(size_t)n * 65 + m + 8]       = acc[ni][2];
        gbuf[(size_t)(n + 1) * 65 + m + 8] = acc[ni][3];
    }
    __syncthreads();

    for (int idx = tid; idx < BM * BHh; idx += THREADS) {
        const int m = idx >> 6, h = idx & 63;
        const int hg = bh0 + h;
        const int b  = bm0 + m;
        const float vi = gbuf[(size_t)(0 * 64 + h) * 65 + m];
        const float vo = gbuf[(size_t)(1 * 64 + h) * 65 + m];
        const float vu = gbuf[(size_t)(2 * 64 + h) * 65 + m];
        const float v0 = gbuf[(size_t)(3 * 64 + h) * 65 + m];
        const float v1 = gbuf[(size_t)(4 * 64 + h) * 65 + m];
        const float ig = sigmf(vi + __ldg(&b_i[hg]));
        const float og = sigmf(vo + __ldg(&b_o[hg]));
        const float ug = tanhf(vu + __ldg(&b_u[hg]));
        const float f0 = sigmf(v0);
        const float f1 = sigmf(v1);
        const float c0 = ch_c[(size_t)b * H + hg];
        const float c1 = ch_c[(size_t)(Bsz + b) * H + hg];
        const float fb = __ldg(&fbias[hg]);
        const float nc = fmaf(ig, ug, fmaf(f0, c0, fmaf(f1, c1, fb * (c0 + c1))));
        const size_t o = (size_t)b * H + hg;
        out[o] = nc;
        out[(size_t)Bsz * H + o] = tanhf(og * nc);
    }
}

extern "C" void kernel_launch(void* const* d_in, const int* in_sizes, int n_in,
                              void* d_out, int out_size) {
    const float* label = (const float*)d_in[0];
    const float* ch_h  = (const float*)d_in[1];
    const float* ch_c  = (const float*)d_in[2];
    const float* W_i   = (const float*)d_in[3];
    const float* b_i   = (const float*)d_in[4];
    const float* W_o   = (const float*)d_in[5];
    const float* b_o   = (const float*)d_in[6];
    const float* W_u   = (const float*)d_in[7];
    const float* b_u   = (const float*)d_in[8];
    const float* W_fl  = (const float*)d_in[9];
    const float* W_fs  = (const float*)d_in[10];
    const float* fb    = (const float*)d_in[11];

    pack_all<<<(NX + NW + 255) / 256, 256>>>(label, ch_h, W_i, W_o, W_u, W_fl, W_fs);

    cudaFuncSetAttribute(treelstm_mma, cudaFuncAttributeMaxDynamicSharedMemorySize, SMEM_TOTAL);
    dim3 grid(H / BHh, Bsz / BM);   // (8, 256)
    treelstm_mma<<<grid, THREADS, SMEM_TOTAL>>>(ch_c, b_i, b_o, b_u, fb, (float*)d_out);
}

// round 12
// speedup vs baseline: 1.4339x; 1.4339x over previous
#include <cuda_runtime.h>
#include <cuda_fp16.h>
#include <cstdint>

// NAryTreeLSTMCell — round 12: 2 CTAs/SM. All 1-CTA/SM variants show the tensor
// pipe idle ~50% (chunk-boundary stalls hit all warps at once). Halved CTA
// (256 thr, BM=64, BK=64, 48KB stages) fits 2 CTAs/SM in RF+SMEM so the two
// CTAs' stall windows interleave. Math identical to r10 (fp16 mma, fp32 acc).
// ARITY=2, LABEL_DIM=128, H_DIM=512, B=16384, ARG_DIM=1152.

namespace {
constexpr int Bsz = 16384;
constexpr int H   = 512;
constexpr int L   = 128;
constexpr int K   = 1152;
constexpr int NG  = 5;
constexpr int BM  = 64;            // batch rows / CTA
constexpr int BNR = 320;           // B rows: 5 gates x 64 h
constexpr int BHh = 64;            // h per gate per CTA
constexpr int BK  = 64;            // K per chunk
constexpr int NCHUNK = K / BK;     // 18
constexpr int THREADS = 256;       // 8 warps: 2(m) x 4(n), warp tile 32x80

constexpr uint32_t AG = BM * 16;    // 1024
constexpr uint32_t BG = BNR * 16;   // 5120
constexpr uint32_t A_TILE = 8 * AG;                // 8192 B  (8 granules/chunk)
constexpr uint32_t B_TILE = 8 * BG;                // 40960 B
constexpr uint32_t OFF_A = 0;
constexpr uint32_t OFF_B = A_TILE;
constexpr uint32_t STAGE_BYTES = A_TILE + B_TILE;  // 49152
constexpr uint32_t SMEM_TOTAL  = 2 * STAGE_BYTES + 64;   // 98368 -> 2 CTAs/SM

constexpr int NX = Bsz * (K / 4);
constexpr int NW = NG * H * (K / 4);
} // namespace

// ---- scratch: chunk-tiled, granule-blocked images (exact SMEM layout) ----
__device__ __half g_Xt[(size_t)NCHUNK * (Bsz / BM) * (A_TILE / 2)];
__device__ __half g_Wt[(size_t)NCHUNK * (H / BHh) * (B_TILE / 2)];

// ---- PTX helpers ----
__device__ __forceinline__ uint32_t smem_u32(const void* p) {
    return (uint32_t)__cvta_generic_to_shared(p);
}
__device__ __forceinline__ void bulk_cp(uint32_t dst, const void* src,
                                        uint32_t bytes, uint32_t mbar) {
    asm volatile("cp.async.bulk.shared::cta.global.mbarrier::complete_tx::bytes "
                 "[%0], [%1], %2, [%3];"
                 :: "r"(dst), "l"(src), "r"(bytes), "r"(mbar) : "memory");
}
__device__ __forceinline__ void mbar_init(uint32_t a, uint32_t cnt) {
    asm volatile("mbarrier.init.shared.b64 [%0], %1;" :: "r"(a), "r"(cnt) : "memory");
}
__device__ __forceinline__ void mbar_expect(uint32_t a, uint32_t bytes) {
    asm volatile("mbarrier.arrive.expect_tx.shared::cta.b64 _, [%0], %1;"
                 :: "r"(a), "r"(bytes) : "memory");
}
__device__ __forceinline__ void mbar_wait(uint32_t a, uint32_t ph) {
    asm volatile("{\n.reg .pred P;\nLW%=:\n"
                 "mbarrier.try_wait.parity.shared::cta.b64 P, [%0], %1;\n"
                 "@!P bra LW%=;\n}" :: "r"(a), "r"(ph) : "memory");
}
__device__ __forceinline__ void ldsm4(uint32_t* r, uint32_t a) {
    asm volatile("ldmatrix.sync.aligned.m8n8.x4.shared.b16 {%0,%1,%2,%3}, [%4];"
                 : "=r"(r[0]), "=r"(r[1]), "=r"(r[2]), "=r"(r[3]) : "r"(a));
}
__device__ __forceinline__ void mma_f16(float* c, const uint32_t* a, const uint32_t* b) {
    asm volatile("mma.sync.aligned.m16n8k16.row.col.f32.f16.f16.f32 "
                 "{%0,%1,%2,%3}, {%4,%5,%6,%7}, {%8,%9}, {%0,%1,%2,%3};"
                 : "+f"(c[0]), "+f"(c[1]), "+f"(c[2]), "+f"(c[3])
                 : "r"(a[0]), "r"(a[1]), "r"(a[2]), "r"(a[3]), "r"(b[0]), "r"(b[1]));
}
__device__ __forceinline__ float sigmf(float x) { return 1.0f / (1.0f + __expf(-x)); }

// ---- merged pack kernel: fp32 -> fp16 tile images for X and W ----
__global__ void pack_all(const float* __restrict__ label, const float* __restrict__ ch_h,
                         const float* __restrict__ Wi, const float* __restrict__ Wo,
                         const float* __restrict__ Wu, const float* __restrict__ Wfl,
                         const float* __restrict__ Wfs) {
    int i = blockIdx.x * blockDim.x + threadIdx.x;
    if (i < NX) {
        int b = i / (K / 4);
        int d = (i % (K / 4)) * 4;
        const float* src;
        if (d < L) src = label + (size_t)b * L + d;
        else {
            int dd = d - L; int j = dd >> 9; int hh = dd & 511;
            src = ch_h + (((size_t)(j * Bsz + b)) << 9) + hh;
        }
        float4 v = *reinterpret_cast<const float4*>(src);
        __half h4[4] = {__float2half_rn(v.x), __float2half_rn(v.y),
                        __float2half_rn(v.z), __float2half_rn(v.w)};
        int c  = d >> 6, kk = d & 63, g = kk >> 3;     // 18 chunks, 8 granules
        int mt = b >> 6, r = b & 63;                   // 256 m-tiles of 64 rows
        size_t o = ((size_t)(c * 256 + mt)) * (A_TILE / 2)
                 + (size_t)g * 512 + r * 8 + (kk & 7);
        *reinterpret_cast<uint2*>(&g_Xt[o]) = *reinterpret_cast<uint2*>(h4);
    } else if (i < NX + NW) {
        int u  = i - NX;
        int rw = u / (K / 4);
        int d  = (u % (K / 4)) * 4;
        int gate = rw >> 9, h = rw & 511;
        const float* src;
        if (gate == 0)      src = Wi + (size_t)h * K + d;
        else if (gate == 1) src = Wo + (size_t)h * K + d;
        else if (gate == 2) src = Wu + (size_t)h * K + d;
        else if (d < L)     src = Wfl + (size_t)h * L + d;
        else {
            int dd = d - L; int j = dd >> 9; int hh = dd & 511;
            src = Wfs + (((size_t)(((gate - 3) * 2 + j) * H + h)) << 9) + hh;
        }
        float4 v = *reinterpret_cast<const float4*>(src);
        __half h4[4] = {__float2half_rn(v.x), __float2half_rn(v.y),
                        __float2half_rn(v.z), __float2half_rn(v.w)};
        int c   = d >> 6, kk = d & 63, g = kk >> 3;
        int bht = h >> 6;
        int rr  = gate * 64 + (h & 63);
        size_t o = ((size_t)(c * 8 + bht)) * (B_TILE / 2)
                 + (size_t)g * 2560 + rr * 8 + (kk & 7);
        *reinterpret_cast<uint2*>(&g_Wt[o]) = *reinterpret_cast<uint2*>(h4);
    }
}

// ---- main kernel ----
__global__ __launch_bounds__(THREADS, 2)
void treelstm_mma(const float* __restrict__ ch_c,
                  const float* __restrict__ b_i, const float* __restrict__ b_o,
                  const float* __restrict__ b_u, const float* __restrict__ fbias,
                  float* __restrict__ out) {
    extern __shared__ char smem[];
    const uint32_t sbase = smem_u32(smem);
    const int tid  = threadIdx.x;
    const int wid  = tid >> 5, lane = tid & 31;
    const int wm   = wid & 1;          // 2 m-warps (32 rows each)
    const int wn   = wid >> 1;         // 4 n-warps (80 cols each)
    const int bht  = blockIdx.x;
    const int mt   = blockIdx.y;
    const int bh0  = bht * BHh;
    const int bm0  = mt * BM;

    const uint32_t STG0 = sbase;
    const uint32_t STG1 = sbase + STAGE_BYTES;
    const uint32_t mb0  = sbase + 2 * STAGE_BYTES;
    const uint32_t mb1  = mb0 + 16;

    const char* Abase = reinterpret_cast<const char*>(g_Xt);
    const char* Bbase = reinterpret_cast<const char*>(g_Wt);
    auto Asrc = [&](int c) { return Abase + ((size_t)(c * 256 + mt)) * A_TILE; };
    auto Bsrc = [&](int c) { return Bbase + ((size_t)(c * 8 + bht)) * B_TILE; };

    if (tid == 0) { mbar_init(mb0, 1); mbar_init(mb1, 1); }
    __syncthreads();
    if (tid == 0) {
        mbar_expect(mb0, STAGE_BYTES);
        bulk_cp(STG0 + OFF_A, Asrc(0), A_TILE, mb0);
        bulk_cp(STG0 + OFF_B, Bsrc(0), B_TILE, mb0);
        mbar_expect(mb1, STAGE_BYTES);
        bulk_cp(STG1 + OFF_A, Asrc(1), A_TILE, mb1);
        bulk_cp(STG1 + OFF_B, Bsrc(1), B_TILE, mb1);
    }

    // ldmatrix lane addressing (granule-blocked, no swizzle)
    const int ar  = ((lane >> 3) & 1) * 8 + (lane & 7);
    const uint32_t aBase = (uint32_t)((wm * 32 + ar) * 16) + (uint32_t)(lane >> 4) * AG;
    const int br  = ((lane >> 4) & 1) * 8 + (lane & 7);
    const uint32_t bBase = (uint32_t)((wn * 80 + br) * 16) + (uint32_t)((lane >> 3) & 1) * BG;

    float acc[2][10][4];               // warp tile 32x80, fp32 masters
    #pragma unroll
    for (int mi = 0; mi < 2; mi++)
        #pragma unroll
        for (int ni = 0; ni < 10; ni++)
            #pragma unroll
            for (int q = 0; q < 4; q++) acc[mi][ni][q] = 0.0f;

    uint32_t ph0 = 0, ph1 = 0;
    for (int k = 0; k < NCHUNK; k++) {
        const int s = k & 1;
        const uint32_t stg = s ? STG1 : STG0;
        if (s) { mbar_wait(mb1, ph1); ph1 ^= 1; }
        else   { mbar_wait(mb0, ph0); ph0 ^= 1; }

        // flattened (ks, np): 20 iterations, one-deep operand ping-pong
        uint32_t A[2][8], Bf[2][4];
        ldsm4(A[0] + 0, stg + OFF_A + aBase);
        ldsm4(A[0] + 4, stg + OFF_A + aBase + 256);
        ldsm4(Bf[0],    stg + OFF_B + bBase);
        #pragma unroll
        for (int it = 0; it < 20; it++) {
            const int ks = it / 5, np = it % 5;
            const int ca = ks & 1, cb = it & 1;
            if (it + 1 < 20) {
                const int ks2 = (it + 1) / 5, np2 = (it + 1) % 5;
                ldsm4(Bf[1 - cb], stg + OFF_B + bBase
                                  + (uint32_t)(2 * ks2) * BG + (uint32_t)np2 * 256);
                if (np2 == 0) {
                    const uint32_t aA = stg + OFF_A + aBase + (uint32_t)(2 * ks2) * AG;
                    ldsm4(A[1 - ca] + 0, aA);
                    ldsm4(A[1 - ca] + 4, aA + 256);
                }
            }
            mma_f16(acc[0][np*2+0], A[ca] + 0, Bf[cb] + 0);
            mma_f16(acc[0][np*2+1], A[ca] + 0, Bf[cb] + 2);
            mma_f16(acc[1][np*2+0], A[ca] + 4, Bf[cb] + 0);
            mma_f16(acc[1][np*2+1], A[ca] + 4, Bf[cb] + 2);
        }
        __syncthreads();                            // stage s fully consumed
        if (k + 2 < NCHUNK && tid == 0) {
            const uint32_t mb = s ? mb1 : mb0;
            mbar_expect(mb, STAGE_BYTES);
            bulk_cp(stg + OFF_A, Asrc(k + 2), A_TILE, mb);
            bulk_cp(stg + OFF_B, Bsrc(k + 2), B_TILE, mb);
        }
    }

    // ---- epilogue: recombine gates through SMEM ----
    __syncthreads();
    float* gbuf = reinterpret_cast<float*>(smem);   // [320][65] = 83KB, fits
    #pragma unroll
    for (int mi = 0; mi < 2; mi++)
        #pragma unroll
        for (int ni = 0; ni < 10; ni++) {
            const int m = wm * 32 + mi * 16 + (lane >> 2);
            const int n = wn * 80 + ni * 8 + 2 * (lane & 3);
            gbuf[(size_t)n * 65 + m]           = acc[mi][ni][0];
            gbuf[(size_t)(n + 1) * 65 + m]     = acc[mi][ni][1];
            gbuf[(size_t)n * 65 + m + 8]       = acc[mi][ni][2];
            gbuf[(size_t)(n + 1) * 65 + m + 8] = acc[mi][ni][3];
        }
    __syncthreads();

    for (int idx = tid; idx < BM * BHh; idx += THREADS) {
        const int m = idx >> 6, h = idx & 63;
        const int hg = bh0 + h;
        const int b  = bm0 + m;
        const float vi = gbuf[(size_t)(0 * 64 + h) * 65 + m];
        const float vo = gbuf[(size_t)(1 * 64 + h) * 65 + m];
        const float vu = gbuf[(size_t)(2 * 64 + h) * 65 + m];
        const float v0 = gbuf[(size_t)(3 * 64 + h) * 65 + m];
        const float v1 = gbuf[(size_t)(4 * 64 + h) * 65 + m];
        const float ig = sigmf(vi + __ldg(&b_i[hg]));
        const float og = sigmf(vo + __ldg(&b_o[hg]));
        const float ug = tanhf(vu + __ldg(&b_u[hg]));
        const float f0 = sigmf(v0);
        const float f1 = sigmf(v1);
        const float c0 = ch_c[(size_t)b * H + hg];
        const float c1 = ch_c[(size_t)(Bsz + b) * H + hg];
        const float fb = __ldg(&fbias[hg]);
        const float nc = fmaf(ig, ug, fmaf(f0, c0, fmaf(f1, c1, fb * (c0 + c1))));
        const size_t o = (size_t)b * H + hg;
        out[o] = nc;
        out[(size_t)Bsz * H + o] = tanhf(og * nc);
    }
}

extern "C" void kernel_launch(void* const* d_in, const int* in_sizes, int n_in,
                              void* d_out, int out_size) {
    const float* label = (const float*)d_in[0];
    const float* ch_h  = (const float*)d_in[1];
    const float* ch_c  = (const float*)d_in[2];
    const float* W_i   = (const float*)d_in[3];
    const float* b_i   = (const float*)d_in[4];
    const float* W_o   = (const float*)d_in[5];
    const float* b_o   = (const float*)d_in[6];
    const float* W_u   = (const float*)d_in[7];
    const float* b_u   = (const float*)d_in[8];
    const float* W_fl  = (const float*)d_in[9];
    const float* W_fs  = (const float*)d_in[10];
    const float* fb    = (const float*)d_in[11];

    pack_all<<<(NX + NW + 255) / 256, 256>>>(label, ch_h, W_i, W_o, W_u, W_fl, W_fs);

    cudaFuncSetAttribute(treelstm_mma, cudaFuncAttributeMaxDynamicSharedMemorySize, SMEM_TOTAL);
    dim3 grid(H / BHh, Bsz / BM);   // (8, 256), 2 CTAs/SM
    treelstm_mma<<<grid, THREADS, SMEM_TOTAL>>>(ch_c, b_i, b_o, b_u, fb, (float*)d_out);
}

// round 13
// speedup vs baseline: 1.4643x; 1.0212x over previous
#include <cuda_runtime.h>
#include <cuda_fp16.h>
#include <cstdint>

// NAryTreeLSTMCell — round 13: warp-granular full/empty mbarrier pipeline.
// r12 (2 CTAs/SM) lifted tensor busy to 58%; the residual idle is the CTA-wide
// __syncthreads at each of the 18 chunk boundaries (all-warp drain + skew).
// This round removes it: per-stage FULL (tx) + EMPTY (count=8) mbarriers; each
// warp waits/arrives independently, only thread 0 gates the bulk-DMA reissue.
// Math identical to r10/r12 (fp16 mma, fp32 acc): rel_err must be 2.1438e-4.
// ARITY=2, LABEL_DIM=128, H_DIM=512, B=16384, ARG_DIM=1152.

namespace {
constexpr int Bsz = 16384;
constexpr int H   = 512;
constexpr int L   = 128;
constexpr int K   = 1152;
constexpr int NG  = 5;
constexpr int BM  = 64;            // batch rows / CTA
constexpr int BNR = 320;           // B rows: 5 gates x 64 h
constexpr int BHh = 64;            // h per gate per CTA
constexpr int BK  = 64;            // K per chunk
constexpr int NCHUNK = K / BK;     // 18
constexpr int THREADS = 256;       // 8 warps: 2(m) x 4(n), warp tile 32x80

constexpr uint32_t AG = BM * 16;    // 1024
constexpr uint32_t BG = BNR * 16;   // 5120
constexpr uint32_t A_TILE = 8 * AG;                // 8192 B
constexpr uint32_t B_TILE = 8 * BG;                // 40960 B
constexpr uint32_t OFF_A = 0;
constexpr uint32_t OFF_B = A_TILE;
constexpr uint32_t STAGE_BYTES = A_TILE + B_TILE;  // 49152
constexpr uint32_t SMEM_TOTAL  = 2 * STAGE_BYTES + 64;   // 98368 -> 2 CTAs/SM

constexpr int NX = Bsz * (K / 4);
constexpr int NW = NG * H * (K / 4);
} // namespace

// ---- scratch: chunk-tiled, granule-blocked images (exact SMEM layout) ----
__device__ __half g_Xt[(size_t)NCHUNK * (Bsz / BM) * (A_TILE / 2)];
__device__ __half g_Wt[(size_t)NCHUNK * (H / BHh) * (B_TILE / 2)];

// ---- PTX helpers ----
__device__ __forceinline__ uint32_t smem_u32(const void* p) {
    return (uint32_t)__cvta_generic_to_shared(p);
}
__device__ __forceinline__ void bulk_cp(uint32_t dst, const void* src,
                                        uint32_t bytes, uint32_t mbar) {
    asm volatile("cp.async.bulk.shared::cta.global.mbarrier::complete_tx::bytes "
                 "[%0], [%1], %2, [%3];"
                 :: "r"(dst), "l"(src), "r"(bytes), "r"(mbar) : "memory");
}
__device__ __forceinline__ void mbar_init(uint32_t a, uint32_t cnt) {
    asm volatile("mbarrier.init.shared.b64 [%0], %1;" :: "r"(a), "r"(cnt) : "memory");
}
__device__ __forceinline__ void mbar_expect(uint32_t a, uint32_t bytes) {
    asm volatile("mbarrier.arrive.expect_tx.shared::cta.b64 _, [%0], %1;"
                 :: "r"(a), "r"(bytes) : "memory");
}
__device__ __forceinline__ void mbar_arrive(uint32_t a) {
    asm volatile("mbarrier.arrive.shared::cta.b64 _, [%0];" :: "r"(a) : "memory");
}
__device__ __forceinline__ void mbar_wait(uint32_t a, uint32_t ph) {
    asm volatile("{\n.reg .pred P;\nLW%=:\n"
                 "mbarrier.try_wait.parity.shared::cta.b64 P, [%0], %1;\n"
                 "@!P bra LW%=;\n}" :: "r"(a), "r"(ph) : "memory");
}
__device__ __forceinline__ void ldsm4(uint32_t* r, uint32_t a) {
    asm volatile("ldmatrix.sync.aligned.m8n8.x4.shared.b16 {%0,%1,%2,%3}, [%4];"
                 : "=r"(r[0]), "=r"(r[1]), "=r"(r[2]), "=r"(r[3]) : "r"(a));
}
__device__ __forceinline__ void mma_f16(float* c, const uint32_t* a, const uint32_t* b) {
    asm volatile("mma.sync.aligned.m16n8k16.row.col.f32.f16.f16.f32 "
                 "{%0,%1,%2,%3}, {%4,%5,%6,%7}, {%8,%9}, {%0,%1,%2,%3};"
                 : "+f"(c[0]), "+f"(c[1]), "+f"(c[2]), "+f"(c[3])
                 : "r"(a[0]), "r"(a[1]), "r"(a[2]), "r"(a[3]), "r"(b[0]), "r"(b[1]));
}
__device__ __forceinline__ float sigmf(float x) { return 1.0f / (1.0f + __expf(-x)); }

// ---- merged pack kernel: fp32 -> fp16 tile images for X and W ----
__global__ void pack_all(const float* __restrict__ label, const float* __restrict__ ch_h,
                         const float* __restrict__ Wi, const float* __restrict__ Wo,
                         const float* __restrict__ Wu, const float* __restrict__ Wfl,
                         const float* __restrict__ Wfs) {
    int i = blockIdx.x * blockDim.x + threadIdx.x;
    if (i < NX) {
        int b = i / (K / 4);
        int d = (i % (K / 4)) * 4;
        const float* src;
        if (d < L) src = label + (size_t)b * L + d;
        else {
            int dd = d - L; int j = dd >> 9; int hh = dd & 511;
            src = ch_h + (((size_t)(j * Bsz + b)) << 9) + hh;
        }
        float4 v = *reinterpret_cast<const float4*>(src);
        __half h4[4] = {__float2half_rn(v.x), __float2half_rn(v.y),
                        __float2half_rn(v.z), __float2half_rn(v.w)};
        int c  = d >> 6, kk = d & 63, g = kk >> 3;     // 18 chunks, 8 granules
        int mt = b >> 6, r = b & 63;                   // 256 m-tiles of 64 rows
        size_t o = ((size_t)(c * 256 + mt)) * (A_TILE / 2)
                 + (size_t)g * 512 + r * 8 + (kk & 7);
        *reinterpret_cast<uint2*>(&g_Xt[o]) = *reinterpret_cast<uint2*>(h4);
    } else if (i < NX + NW) {
        int u  = i - NX;
        int rw = u / (K / 4);
        int d  = (u % (K / 4)) * 4;
        int gate = rw >> 9, h = rw & 511;
        const float* src;
        if (gate == 0)      src = Wi + (size_t)h * K + d;
        else if (gate == 1) src = Wo + (size_t)h * K + d;
        else if (gate == 2) src = Wu + (size_t)h * K + d;
        else if (d < L)     src = Wfl + (size_t)h * L + d;
        else {
            int dd = d - L; int j = dd >> 9; int hh = dd & 511;
            src = Wfs + (((size_t)(((gate - 3) * 2 + j) * H + h)) << 9) + hh;
        }
        float4 v = *reinterpret_cast<const float4*>(src);
        __half h4[4] = {__float2half_rn(v.x), __float2half_rn(v.y),
                        __float2half_rn(v.z), __float2half_rn(v.w)};
        int c   = d >> 6, kk = d & 63, g = kk >> 3;
        int bht = h >> 6;
        int rr  = gate * 64 + (h & 63);
        size_t o = ((size_t)(c * 8 + bht)) * (B_TILE / 2)
                 + (size_t)g * 2560 + rr * 8 + (kk & 7);
        *reinterpret_cast<uint2*>(&g_Wt[o]) = *reinterpret_cast<uint2*>(h4);
    }
}

// ---- main kernel ----
__global__ __launch_bounds__(THREADS, 2)
void treelstm_mma(const float* __restrict__ ch_c,
                  const float* __restrict__ b_i, const float* __restrict__ b_o,
                  const float* __restrict__ b_u, const float* __restrict__ fbias,
                  float* __restrict__ out) {
    extern __shared__ char smem[];
    const uint32_t sbase = smem_u32(smem);
    const int tid  = threadIdx.x;
    const int wid  = tid >> 5, lane = tid & 31;
    const int wm   = wid & 1;          // 2 m-warps (32 rows each)
    const int wn   = wid >> 1;         // 4 n-warps (80 cols each)
    const int bht  = blockIdx.x;
    const int mt   = blockIdx.y;
    const int bh0  = bht * BHh;
    const int bm0  = mt * BM;

    const uint32_t STG0 = sbase;
    const uint32_t STG1 = sbase + STAGE_BYTES;
    const uint32_t mbF0 = sbase + 2 * STAGE_BYTES;        // full barriers (tx)
    const uint32_t mbF1 = mbF0 + 8;
    const uint32_t mbE0 = mbF0 + 16;                      // empty barriers (8 arrivals)
    const uint32_t mbE1 = mbF0 + 24;

    const char* Abase = reinterpret_cast<const char*>(g_Xt);
    const char* Bbase = reinterpret_cast<const char*>(g_Wt);
    auto Asrc = [&](int c) { return Abase + ((size_t)(c * 256 + mt)) * A_TILE; };
    auto Bsrc = [&](int c) { return Bbase + ((size_t)(c * 8 + bht)) * B_TILE; };

    if (tid == 0) {
        mbar_init(mbF0, 1);  mbar_init(mbF1, 1);
        mbar_init(mbE0, 8);  mbar_init(mbE1, 8);
    }
    __syncthreads();
    if (tid == 0) {
        mbar_expect(mbF0, STAGE_BYTES);
        bulk_cp(STG0 + OFF_A, Asrc(0), A_TILE, mbF0);
        bulk_cp(STG0 + OFF_B, Bsrc(0), B_TILE, mbF0);
        mbar_expect(mbF1, STAGE_BYTES);
        bulk_cp(STG1 + OFF_A, Asrc(1), A_TILE, mbF1);
        bulk_cp(STG1 + OFF_B, Bsrc(1), B_TILE, mbF1);
    }

    // ldmatrix lane addressing (granule-blocked, no swizzle)
    const int ar  = ((lane >> 3) & 1) * 8 + (lane & 7);
    const uint32_t aBase = (uint32_t)((wm * 32 + ar) * 16) + (uint32_t)(lane >> 4) * AG;
    const int br  = ((lane >> 4) & 1) * 8 + (lane & 7);
    const uint32_t bBase = (uint32_t)((wn * 80 + br) * 16) + (uint32_t)((lane >> 3) & 1) * BG;

    float acc[2][10][4];               // warp tile 32x80, fp32 masters
    #pragma unroll
    for (int mi = 0; mi < 2; mi++)
        #pragma unroll
        for (int ni = 0; ni < 10; ni++)
            #pragma unroll
            for (int q = 0; q < 4; q++) acc[mi][ni][q] = 0.0f;

    uint32_t phf0 = 0, phf1 = 0;       // per-warp full phases
    uint32_t phe0 = 0, phe1 = 0;       // producer-only empty phases
    for (int k = 0; k < NCHUNK; k++) {
        const int s = k & 1;
        const uint32_t stg = s ? STG1 : STG0;
        if (s) { mbar_wait(mbF1, phf1); phf1 ^= 1; }
        else   { mbar_wait(mbF0, phf0); phf0 ^= 1; }

        // flattened (ks, np): 20 iterations, one-deep operand ping-pong
        uint32_t A[2][8], Bf[2][4];
        ldsm4(A[0] + 0, stg + OFF_A + aBase);
        ldsm4(A[0] + 4, stg + OFF_A + aBase + 256);
        ldsm4(Bf[0],    stg + OFF_B + bBase);
        #pragma unroll
        for (int it = 0; it < 20; it++) {
            const int ks = it / 5, np = it % 5;
            const int ca = ks & 1, cb = it & 1;
            if (it + 1 < 20) {
                const int ks2 = (it + 1) / 5, np2 = (it + 1) % 5;
                ldsm4(Bf[1 - cb], stg + OFF_B + bBase
                                  + (uint32_t)(2 * ks2) * BG + (uint32_t)np2 * 256);
                if (np2 == 0) {
                    const uint32_t aA = stg + OFF_A + aBase + (uint32_t)(2 * ks2) * AG;
                    ldsm4(A[1 - ca] + 0, aA);
                    ldsm4(A[1 - ca] + 4, aA + 256);
                }
            }
            mma_f16(acc[0][np*2+0], A[ca] + 0, Bf[cb] + 0);
            mma_f16(acc[0][np*2+1], A[ca] + 0, Bf[cb] + 2);
            mma_f16(acc[1][np*2+0], A[ca] + 4, Bf[cb] + 0);
            mma_f16(acc[1][np*2+1], A[ca] + 4, Bf[cb] + 2);
        }
        // this warp is done with stage s
        if (lane == 0) mbar_arrive(s ? mbE1 : mbE0);
        // producer: wait all 8 warps done, then refill stage s for chunk k+2
        if (tid == 0 && k + 2 < NCHUNK) {
            if (s) { mbar_wait(mbE1, phe1); phe1 ^= 1; }
            else   { mbar_wait(mbE0, phe0); phe0 ^= 1; }
            const uint32_t mb = s ? mbF1 : mbF0;
            mbar_expect(mb, STAGE_BYTES);
            bulk_cp(stg + OFF_A, Asrc(k + 2), A_TILE, mb);
            bulk_cp(stg + OFF_B, Bsrc(k + 2), B_TILE, mb);
        }
    }

    // ---- epilogue: recombine gates through SMEM ----
    __syncthreads();                    // all warps out of mainloop, DMA drained
    float* gbuf = reinterpret_cast<float*>(smem);   // [320][65] = 83KB, fits
    #pragma unroll
    for (int mi = 0; mi < 2; mi++)
        #pragma unroll
        for (int ni = 0; ni < 10; ni++) {
            const int m = wm * 32 + mi * 16 + (lane >> 2);
            const int n = wn * 80 + ni * 8 + 2 * (lane & 3);
            gbuf[(size_t)n * 65 + m]           = acc[mi][ni][0];
            gbuf[(size_t)(n + 1) * 65 + m]     = acc[mi][ni][1];
            gbuf[(size_t)n * 65 + m + 8]       = acc[mi][ni][2];
            gbuf[(size_t)(n + 1) * 65 + m + 8] = acc[mi][ni][3];
        }
    __syncthreads();

    for (int idx = tid; idx < BM * BHh; idx += THREADS) {
        const int m = idx >> 6, h = idx & 63;
        const int hg = bh0 + h;
        const int b  = bm0 + m;
        const float vi = gbuf[(size_t)(0 * 64 + h) * 65 + m];
        const float vo = gbuf[(size_t)(1 * 64 + h) * 65 + m];
        const float vu = gbuf[(size_t)(2 * 64 + h) * 65 + m];
        const float v0 = gbuf[(size_t)(3 * 64 + h) * 65 + m];
        const float v1 = gbuf[(size_t)(4 * 64 + h) * 65 + m];
        const float ig = sigmf(vi + __ldg(&b_i[hg]));
        const float og = sigmf(vo + __ldg(&b_o[hg]));
        const float ug = tanhf(vu + __ldg(&b_u[hg]));
        const float f0 = sigmf(v0);
        const float f1 = sigmf(v1);
        const float c0 = ch_c[(size_t)b * H + hg];
        const float c1 = ch_c[(size_t)(Bsz + b) * H + hg];
        const float fb = __ldg(&fbias[hg]);
        const float nc = fmaf(ig, ug, fmaf(f0, c0, fmaf(f1, c1, fb * (c0 + c1))));
        const size_t o = (size_t)b * H + hg;
        out[o] = nc;
        out[(size_t)Bsz * H + o] = tanhf(og * nc);
    }
}

extern "C" void kernel_launch(void* const* d_in, const int* in_sizes, int n_in,
                              void* d_out, int out_size) {
    const float* label = (const float*)d_in[0];
    const float* ch_h  = (const float*)d_in[1];
    const float* ch_c  = (const float*)d_in[2];
    const float* W_i   = (const float*)d_in[3];
    const float* b_i   = (const float*)d_in[4];
    const float* W_o   = (const float*)d_in[5];
    const float* b_o   = (const float*)d_in[6];
    const float* W_u   = (const float*)d_in[7];
    const float* b_u   = (const float*)d_in[8];
    const float* W_fl  = (const float*)d_in[9];
    const float* W_fs  = (const float*)d_in[10];
    const float* fb    = (const float*)d_in[11];

    pack_all<<<(NX + NW + 255) / 256, 256>>>(label, ch_h, W_i, W_o, W_u, W_fl, W_fs);

    cudaFuncSetAttribute(treelstm_mma, cudaFuncAttributeMaxDynamicSharedMemorySize, SMEM_TOTAL);
    dim3 grid(H / BHh, Bsz / BM);   // (8, 256), 2 CTAs/SM
    treelstm_mma<<<grid, THREADS, SMEM_TOTAL>>>(ch_c, b_i, b_o, b_u, fb, (float*)d_out);
}